// round 10
// baseline (speedup 1.0000x reference)
#include <cuda_runtime.h>
#include <cstdint>

#define HW 16384          // 128*128
#define NB 4
#define NG 4
#define K2 9

typedef unsigned long long ull;

#define FMA2(d, a, b, c) \
    asm("fma.rn.f32x2 %0, %1, %2, %3;" : "=l"(d) : "l"(a), "l"(b), "l"(c))
#define PACKF(dst, lo, hi) \
    asm("mov.b64 %0, {%1, %2};" : "=l"(dst) : "r"(__float_as_uint(lo)), "r"(__float_as_uint(hi)))
#define UNPACKF(lo, hi, src) \
    asm("mov.b64 {%0, %1}, %2;" : "=r"(lo), "=r"(hi) : "l"(src))

// Scratch (allocation-free __device__ globals)
__device__ __align__(16) float g_off[NB * NG * 18 * HW];     // [slice][o][px]  o=2k:dy 2k+1:dx
__device__ __align__(16) float g_mask[NB * K2 * HW];         // [b][k][px]
__device__ __align__(16) float2 g_wf2[5 * 16 * 18 * 9];      // folded 3x3 {w,w}: [j][ic][o][t]
__device__ __align__(16) float2 g_w12[5 * 48 * 18];          // 1x1 remainder {w,w}: [j][c][o]

// ---------------------------------------------------------------------------
// Fold: g_wf2[j][ic][o][t] = {s,s}, s = sum_c headW[j][o][c] * convW[j][c][ic][t]
//       g_w12[j][c][o]     = {headW[j][o][16+c]} x2
// ---------------------------------------------------------------------------
__global__ void fold_kernel(
    const float* __restrict__ mask_pw,  // (16,16,3,3)
    const float* __restrict__ mask_w,   // (9,64)
    const float* __restrict__ off_pw,   // (4,16,16,3,3)
    const float* __restrict__ off_w)    // (4,18,64)
{
    int idx = blockIdx.x * 256 + threadIdx.x;
    for (int e = idx; e < 5 * 16 * 18 * 9; e += gridDim.x * 256) {
        int j  = e / 2592;
        int r  = e - j * 2592;
        int ic = r / 162;
        int r2 = r - ic * 162;
        int o  = r2 / 9;
        int t  = r2 - o * 9;
        float s = 0.f;
        if (!(j == 0 && o >= 9)) {
            const float* hw = (j == 0) ? (mask_w + o * 64)
                                       : (off_w + ((j - 1) * 18 + o) * 64);
            const float* cw = (j == 0) ? mask_pw : (off_pw + (j - 1) * 2304);
#pragma unroll
            for (int c = 0; c < 16; c++)
                s = fmaf(hw[c], cw[c * 144 + ic * 9 + t], s);
        }
        g_wf2[e] = make_float2(s, s);
    }
    for (int e = idx; e < 5 * 48 * 18; e += gridDim.x * 256) {
        int j = e / (48 * 18);
        int r = e - j * 48 * 18;
        int c = r / 18;
        int o = r - c * 18;
        float s = 0.f;
        if (!(j == 0 && o >= 9)) {
            const float* hw = (j == 0) ? (mask_w + o * 64)
                                       : (off_w + ((j - 1) * 18 + o) * 64);
            s = hw[16 + c];
        }
        g_w12[e] = make_float2(s, s);
    }
}

// ---------------------------------------------------------------------------
// Fused head: (3x3 conv 16->NO folded) + (1x1 48->NO) + bias, f32x2 packed.
// grid (4, 8, NB*5): tile h=16, w=32.  block 128 = 2 output-halves x 64 px-grps.
// Thread: 8 px (4 f32x2 pairs) x 9 outputs.  j=0: mask+sigmoid, j>=1: offsets.
// Weights read directly from global (warp-uniform LDG, L1-cached).
// Dynamic smem: s_in[16][18][34] only (39 KB) -> 5 blocks/SM.
// ---------------------------------------------------------------------------
__global__ __launch_bounds__(128) void fused_head_kernel(
    const float* __restrict__ x,
    const float* __restrict__ mask_b,   // (9,)
    const float* __restrict__ off_b)    // (4,18)
{
    extern __shared__ float s_in[];                // 16*18*34 = 9792 floats

    const int bz = blockIdx.z;
    const int j  = bz % 5;        // 0 = mask head, 1..4 = offset head g=j-1
    const int b  = bz / 5;
    const int h0 = blockIdx.y * 16;
    const int w0 = blockIdx.x * 32;
    const int tid = threadIdx.x;

    const float* xb = x + (size_t)b * 64 * HW;
    for (int idx = tid; idx < 9792; idx += 128) {
        int ic  = idx / 612;
        int rem = idx - ic * 612;
        int ly  = rem / 34;
        int lx  = rem - ly * 34;
        int gy = h0 - 1 + ly;
        int gx = w0 - 1 + lx;
        float v = 0.f;
        if ((unsigned)gy < 128u && (unsigned)gx < 128u)
            v = xb[ic * HW + gy * 128 + gx];
        s_in[idx] = v;
    }
    __syncthreads();

    const int oh  = tid >> 6;        // output half: o_global = oh*9 + o
    const int grp = tid & 63;
    const int r   = grp >> 2;        // row 0..15
    const int c0  = (grp & 3) * 8;   // col base 0,8,16,24

    if (j == 0 && oh == 1) return;   // mask head has only 9 outputs

    ull acc2[9][4];
#pragma unroll
    for (int o = 0; o < 9; o++) {
        float bb = (j == 0) ? mask_b[o] : off_b[(j - 1) * 18 + oh * 9 + o];
        ull bv; PACKF(bv, bb, bb);
#pragma unroll
        for (int q = 0; q < 4; q++) acc2[o][q] = bv;
    }

    // 3x3 folded part (weights: warp-uniform global loads)
    const ull* wbase = (const ull*)(g_wf2 + j * 2592 + oh * 81);
#pragma unroll 1
    for (int ic = 0; ic < 16; ic++) {
        const float* rb = s_in + ic * 612 + r * 34 + c0;
        const ull* wb = wbase + ic * 162;
#pragma unroll
        for (int dy = 0; dy < 3; dy++) {
            float v[10];
            const float* rp = rb + dy * 34;
#pragma unroll
            for (int i = 0; i < 10; i++) v[i] = rp[i];
            ull vp[9];
#pragma unroll
            for (int i = 0; i < 9; i++) PACKF(vp[i], v[i], v[i + 1]);
#pragma unroll
            for (int o = 0; o < 9; o++) {
#pragma unroll
                for (int dx = 0; dx < 3; dx++) {
                    ull w2 = __ldg(&wb[o * 9 + dy * 3 + dx]);
                    FMA2(acc2[o][0], w2, vp[dx + 0], acc2[o][0]);
                    FMA2(acc2[o][1], w2, vp[dx + 2], acc2[o][1]);
                    FMA2(acc2[o][2], w2, vp[dx + 4], acc2[o][2]);
                    FMA2(acc2[o][3], w2, vp[dx + 6], acc2[o][3]);
                }
            }
        }
    }

    // 1x1 remainder over x[16:64]
    const int pxb = (h0 + r) * 128 + w0 + c0;
    const float* xr = xb + 16 * HW + pxb;
    const ull* w1base = (const ull*)(g_w12 + j * 864 + oh * 9);
#pragma unroll 2
    for (int c = 0; c < 48; c++) {
        ulonglong2 u01 = *(const ulonglong2*)(xr + (size_t)c * HW);
        ulonglong2 u23 = *(const ulonglong2*)(xr + (size_t)c * HW + 4);
        const ull* wp = w1base + c * 18;
#pragma unroll
        for (int o = 0; o < 9; o++) {
            ull w2 = __ldg(&wp[o]);
            FMA2(acc2[o][0], w2, u01.x, acc2[o][0]);
            FMA2(acc2[o][1], w2, u01.y, acc2[o][1]);
            FMA2(acc2[o][2], w2, u23.x, acc2[o][2]);
            FMA2(acc2[o][3], w2, u23.y, acc2[o][3]);
        }
    }

    if (j == 0) {
        float* mp = g_mask + (size_t)b * 9 * HW + pxb;
#pragma unroll
        for (int o = 0; o < 9; o++) {
            float f[8];
#pragma unroll
            for (int q = 0; q < 4; q++) {
                unsigned lo, hi; UNPACKF(lo, hi, acc2[o][q]);
                f[2 * q]     = 1.f / (1.f + __expf(-__uint_as_float(lo)));
                f[2 * q + 1] = 1.f / (1.f + __expf(-__uint_as_float(hi)));
            }
            float* dst = mp + (size_t)o * HW;
            *reinterpret_cast<float4*>(dst)     = make_float4(f[0], f[1], f[2], f[3]);
            *reinterpret_cast<float4*>(dst + 4) = make_float4(f[4], f[5], f[6], f[7]);
        }
    } else {
        const int slice = b * 4 + (j - 1);
        float* op = g_off + ((size_t)slice * 18 + oh * 9) * HW + pxb;
#pragma unroll
        for (int o = 0; o < 9; o++) {
            float* dst = op + (size_t)o * HW;
            ulonglong2 s0; s0.x = acc2[o][0]; s0.y = acc2[o][1];
            ulonglong2 s1; s1.x = acc2[o][2]; s1.y = acc2[o][3];
            *reinterpret_cast<ulonglong2*>(dst)     = s0;
            *reinterpret_cast<ulonglong2*>(dst + 4) = s1;
        }
    }
}

// ---------------------------------------------------------------------------
// Sampler: thread = (b, g, channel-group of 4, h, pixel-pair).  524288 threads.
// Corner indices/weights in registers per tap, reused over 4 ch x 2 images.
// ---------------------------------------------------------------------------
__global__ __launch_bounds__(256, 5) void sample_kernel(
    const float* __restrict__ y, float* __restrict__ out)
{
    int idx = blockIdx.x * 256 + threadIdx.x;
    const int w2 = idx & 63;  idx >>= 6;
    const int h  = idx & 127; idx >>= 7;
    const int cg = idx & 3;   idx >>= 2;
    const int g  = idx & 3;
    const int b  = idx >> 2;
    const int w  = w2 * 2;
    const int px = h * 128 + w;

    const float* off = g_off + (size_t)(b * 4 + g) * 18 * HW;
    const float* msk = g_mask + (size_t)b * 9 * HW;
    const float* y1  = y + (size_t)(b * 64 + g * 16 + cg * 4) * HW;
    const float* y2  = y + (size_t)((b + 4) * 64 + g * 16 + cg * 4) * HW;
    float* o1 = out + ((size_t)(b * 64 + g * 16 + cg * 4) * 9) * HW + px;
    float* o2 = out + ((size_t)((b + 4) * 64 + g * 16 + cg * 4) * 9) * HW + px;

    const int dil = 2 * g + 1;

#pragma unroll 1
    for (int k = 0; k < 9; k++) {
        const int ky = k / 3 - 1;
        const int kx = k % 3 - 1;
        const float basey = (float)(h + ky * dil);
        const float basex = (float)(w + kx * dil);

        const float2 dy2 = *reinterpret_cast<const float2*>(off + (size_t)(2 * k) * HW + px);
        const float2 dx2 = *reinterpret_cast<const float2*>(off + (size_t)(2 * k + 1) * HW + px);
        const float2 m2  = *reinterpret_cast<const float2*>(msk + (size_t)k * HW + px);

        int   ci[2][4];
        float cw[2][4];
#pragma unroll
        for (int p = 0; p < 2; p++) {
            float py  = basey + (p ? dy2.y : dy2.x);
            float pxx = basex + (float)p + (p ? dx2.y : dx2.x);
            float m   = p ? m2.y : m2.x;

            float fy0 = floorf(py);
            float fx0 = floorf(pxx);
            float wy = py - fy0;
            float wx = pxx - fx0;

            bool vy0 = (fy0 >= 0.f)  && (fy0 <= 127.f);
            bool vy1 = (fy0 >= -1.f) && (fy0 <= 126.f);
            bool vx0 = (fx0 >= 0.f)  && (fx0 <= 127.f);
            bool vx1 = (fx0 >= -1.f) && (fx0 <= 126.f);

            int y0c = (int)fminf(fmaxf(fy0,       0.f), 127.f);
            int y1c = (int)fminf(fmaxf(fy0 + 1.f, 0.f), 127.f);
            int x0c = (int)fminf(fmaxf(fx0,       0.f), 127.f);
            int x1c = (int)fminf(fmaxf(fx0 + 1.f, 0.f), 127.f);

            float w00 = (1.f - wy) * (1.f - wx) * m; if (!(vy0 && vx0)) w00 = 0.f;
            float w01 = (1.f - wy) * wx        * m; if (!(vy0 && vx1)) w01 = 0.f;
            float w10 = wy        * (1.f - wx) * m; if (!(vy1 && vx0)) w10 = 0.f;
            float w11 = wy        * wx         * m; if (!(vy1 && vx1)) w11 = 0.f;

            ci[p][0] = y0c * 128 + x0c;  cw[p][0] = w00;
            ci[p][1] = y0c * 128 + x1c;  cw[p][1] = w01;
            ci[p][2] = y1c * 128 + x0c;  cw[p][2] = w10;
            ci[p][3] = y1c * 128 + x1c;  cw[p][3] = w11;
        }

#pragma unroll
        for (int c = 0; c < 4; c++) {
            const float* s1 = y1 + (size_t)c * HW;
            const float* s2 = y2 + (size_t)c * HW;

            float r1x = cw[0][0] * s1[ci[0][0]] + cw[0][1] * s1[ci[0][1]]
                      + cw[0][2] * s1[ci[0][2]] + cw[0][3] * s1[ci[0][3]];
            float r1y = cw[1][0] * s1[ci[1][0]] + cw[1][1] * s1[ci[1][1]]
                      + cw[1][2] * s1[ci[1][2]] + cw[1][3] * s1[ci[1][3]];
            float r2x = cw[0][0] * s2[ci[0][0]] + cw[0][1] * s2[ci[0][1]]
                      + cw[0][2] * s2[ci[0][2]] + cw[0][3] * s2[ci[0][3]];
            float r2y = cw[1][0] * s2[ci[1][0]] + cw[1][1] * s2[ci[1][1]]
                      + cw[1][2] * s2[ci[1][2]] + cw[1][3] * s2[ci[1][3]];

            *reinterpret_cast<float2*>(o1 + (size_t)(c * 9 + k) * HW) = make_float2(r1x, r1y);
            *reinterpret_cast<float2*>(o2 + (size_t)(c * 9 + k) * HW) = make_float2(r2x, r2y);
        }
    }
}

// ---------------------------------------------------------------------------
extern "C" void kernel_launch(void* const* d_in, const int* in_sizes, int n_in,
                              void* d_out, int out_size)
{
    const float *x = nullptr, *y = nullptr, *off_pw = nullptr, *off_w = nullptr,
                *off_b = nullptr, *mask_pw = nullptr, *mask_w = nullptr, *mask_b = nullptr;
    for (int i = 0; i < n_in; i++) {
        switch (in_sizes[i]) {
            case 4194304: x       = (const float*)d_in[i]; break;
            case 8388608: y       = (const float*)d_in[i]; break;
            case 9216:    off_pw  = (const float*)d_in[i]; break;
            case 4608:    off_w   = (const float*)d_in[i]; break;
            case 72:      off_b   = (const float*)d_in[i]; break;
            case 2304:    mask_pw = (const float*)d_in[i]; break;
            case 576:     mask_w  = (const float*)d_in[i]; break;
            case 9:       mask_b  = (const float*)d_in[i]; break;
            default: break;
        }
    }
    float* out = (float*)d_out;

    const int head_smem = 9792 * 4;   // 39168 bytes: input tile only
    cudaFuncSetAttribute(fused_head_kernel,
                         cudaFuncAttributeMaxDynamicSharedMemorySize, head_smem);

    fold_kernel<<<56, 256>>>(mask_pw, mask_w, off_pw, off_w);
    fused_head_kernel<<<dim3(4, 8, NB * 5), 128, head_smem>>>(x, mask_b, off_b);
    sample_kernel<<<2048, 256>>>(y, out);
}

// round 17
// speedup vs baseline: 1.2543x; 1.2543x over previous
#include <cuda_runtime.h>
#include <cstdint>

#define HW 16384          // 128*128
#define NB 4
#define NG 4
#define K2 9

typedef unsigned long long ull;

#define FMA2(d, a, b, c) \
    asm("fma.rn.f32x2 %0, %1, %2, %3;" : "=l"(d) : "l"(a), "l"(b), "l"(c))
#define PACKF(dst, lo, hi) \
    asm("mov.b64 %0, {%1, %2};" : "=l"(dst) : "r"(__float_as_uint(lo)), "r"(__float_as_uint(hi)))
#define UNPACKF(lo, hi, src) \
    asm("mov.b64 {%0, %1}, %2;" : "=r"(lo), "=r"(hi) : "l"(src))

// Scratch (allocation-free __device__ globals)
__device__ __align__(16) float g_off[NB * NG * 18 * HW];  // [slice][o][px] o=2k:dy 2k+1:dx
__device__ __align__(16) float g_mask[NB * K2 * HW];      // [b][k][px]
// Packed weights per head j (3648 ull):
//   [0,2688):  3x3 folded  [(oh*16+ic)*3+dy]*28 + u,  u=0..26 -> (o=u/3, dx=u%3), u=27 pad
//   [2688,3648): 1x1       2688 + (c*2+oh)*10 + u,    u=0..8 -> o, u=9 pad
__device__ __align__(16) float2 g_wp[5 * 3648];

// ---------------------------------------------------------------------------
// Fold kernel (runs once, ~6us): builds packed duplicated {s,s} weights.
// ---------------------------------------------------------------------------
__global__ void fold_kernel(
    const float* __restrict__ mask_pw,  // (16,16,3,3)
    const float* __restrict__ mask_w,   // (9,64)
    const float* __restrict__ off_pw,   // (4,16,16,3,3)
    const float* __restrict__ off_w)    // (4,18,64)
{
    int idx = blockIdx.x * 256 + threadIdx.x;
    // 3x3 part: 5 * 2 * 16 * 3 * 28 = 13440 entries
    for (int e = idx; e < 13440; e += gridDim.x * 256) {
        int u    = e % 28;
        int rest = e / 28;
        int dy   = rest % 3;  rest /= 3;
        int ic   = rest % 16; rest /= 16;
        int oh   = rest % 2;
        int j    = rest / 2;
        float s = 0.f;
        if (u < 27) {
            int o  = oh * 9 + u / 3;
            int dx = u % 3;
            int t  = dy * 3 + dx;
            if (!(j == 0 && o >= 9)) {
                const float* hw = (j == 0) ? (mask_w + o * 64)
                                           : (off_w + ((j - 1) * 18 + o) * 64);
                const float* cw = (j == 0) ? mask_pw : (off_pw + (j - 1) * 2304);
#pragma unroll
                for (int c = 0; c < 16; c++)
                    s = fmaf(hw[c], cw[c * 144 + ic * 9 + t], s);
            }
        }
        g_wp[j * 3648 + ((oh * 16 + ic) * 3 + dy) * 28 + u] = make_float2(s, s);
    }
    // 1x1 part: 5 * 48 * 2 * 10 = 4800 entries
    for (int e = idx; e < 4800; e += gridDim.x * 256) {
        int u    = e % 10;
        int rest = e / 10;
        int oh   = rest % 2;  rest /= 2;
        int c    = rest % 48;
        int j    = rest / 48;
        float s = 0.f;
        if (u < 9) {
            int o = oh * 9 + u;
            if (!(j == 0 && o >= 9)) {
                const float* hw = (j == 0) ? (mask_w + o * 64)
                                           : (off_w + ((j - 1) * 18 + o) * 64);
                s = hw[16 + c];
            }
        }
        g_wp[j * 3648 + 2688 + (c * 2 + oh) * 10 + u] = make_float2(s, s);
    }
}

// ---------------------------------------------------------------------------
// Fused head: (3x3 conv 16->NO folded) + (1x1 48->NO) + bias, f32x2 packed.
// grid (4, 8, NB*5): tile h=16, w=32.  block 128 = 2 output-halves x 64 px-grps.
// Thread: 8 px (4 f32x2 pairs) x 9 outputs.
// smem: s_in[8][18][34] (one ic-phase, 19.6KB) + packed weights (29.2KB) = 48.8KB
// -> 4 blocks/SM.  Weight LDS vectorized to 128-bit.
// ---------------------------------------------------------------------------
__global__ __launch_bounds__(128) void fused_head_kernel(
    const float* __restrict__ x,
    const float* __restrict__ mask_b,   // (9,)
    const float* __restrict__ off_b)    // (4,18)
{
    extern __shared__ float smem[];
    float* s_in = smem;                            // 4896 floats
    ull*   s_w  = (ull*)(smem + 4896);             // 3648 ull

    const int bz = blockIdx.z;
    const int j  = bz % 5;        // 0 = mask head, 1..4 = offset head g=j-1
    const int b  = bz / 5;
    const int h0 = blockIdx.y * 16;
    const int w0 = blockIdx.x * 32;
    const int tid = threadIdx.x;

    const float* xb = x + (size_t)b * 64 * HW;

    // stage packed weights once
    {
        const ull* src = (const ull*)(g_wp + j * 3648);
        for (int i = tid; i < 3648; i += 128) s_w[i] = src[i];
    }

    const int oh  = tid >> 6;        // output half: o_global = oh*9 + o
    const int grp = tid & 63;
    const int r   = grp >> 2;        // row 0..15
    const int c0  = (grp & 3) * 8;   // col base 0,8,16,24
    const bool active = !(j == 0 && oh == 1);

    ull acc2[9][4];
#pragma unroll
    for (int o = 0; o < 9; o++) {
        float bb = (j == 0) ? mask_b[o] : off_b[(j - 1) * 18 + oh * 9 + o];
        ull bv; PACKF(bv, bb, bb);
#pragma unroll
        for (int q = 0; q < 4; q++) acc2[o][q] = bv;
    }

    // two ic phases of 8 channels each
#pragma unroll 1
    for (int phase = 0; phase < 2; phase++) {
        if (phase) __syncthreads();   // previous compute done before overwrite
        for (int idx = tid; idx < 4896; idx += 128) {
            int icl = idx / 612;
            int rem = idx - icl * 612;
            int ly  = rem / 34;
            int lx  = rem - ly * 34;
            int gy = h0 - 1 + ly;
            int gx = w0 - 1 + lx;
            float v = 0.f;
            if ((unsigned)gy < 128u && (unsigned)gx < 128u)
                v = xb[(phase * 8 + icl) * HW + gy * 128 + gx];
            s_in[idx] = v;
        }
        __syncthreads();

        if (!active) continue;

#pragma unroll 1
        for (int icl = 0; icl < 8; icl++) {
            const int ic = phase * 8 + icl;
            const float* rb  = s_in + icl * 612 + r * 34 + c0;
            const ull*   wic = s_w + ((oh * 16 + ic) * 3) * 28;
#pragma unroll 1
            for (int dy = 0; dy < 3; dy++) {
                float v[10];
                const float* rp = rb + dy * 34;
#pragma unroll
                for (int i = 0; i < 10; i++) v[i] = rp[i];
                ull vp[9];
#pragma unroll
                for (int i = 0; i < 9; i++) PACKF(vp[i], v[i], v[i + 1]);

                const ull* wb = wic + dy * 28;
#pragma unroll
                for (int u2 = 0; u2 < 13; u2++) {
                    ulonglong2 wpair = *(const ulonglong2*)(wb + 2 * u2);
                    const int t0 = 2 * u2,     o0 = t0 / 3, dx0 = t0 % 3;
                    const int t1 = 2 * u2 + 1, o1 = t1 / 3, dx1 = t1 % 3;
                    FMA2(acc2[o0][0], wpair.x, vp[dx0 + 0], acc2[o0][0]);
                    FMA2(acc2[o0][1], wpair.x, vp[dx0 + 2], acc2[o0][1]);
                    FMA2(acc2[o0][2], wpair.x, vp[dx0 + 4], acc2[o0][2]);
                    FMA2(acc2[o0][3], wpair.x, vp[dx0 + 6], acc2[o0][3]);
                    FMA2(acc2[o1][0], wpair.y, vp[dx1 + 0], acc2[o1][0]);
                    FMA2(acc2[o1][1], wpair.y, vp[dx1 + 2], acc2[o1][1]);
                    FMA2(acc2[o1][2], wpair.y, vp[dx1 + 4], acc2[o1][2]);
                    FMA2(acc2[o1][3], wpair.y, vp[dx1 + 6], acc2[o1][3]);
                }
                {   // u = 26 -> o=8, dx=2
                    ull wl = wb[26];
                    FMA2(acc2[8][0], wl, vp[2], acc2[8][0]);
                    FMA2(acc2[8][1], wl, vp[4], acc2[8][1]);
                    FMA2(acc2[8][2], wl, vp[6], acc2[8][2]);
                    FMA2(acc2[8][3], wl, vp[8], acc2[8][3]);
                }
            }
        }
    }

    if (!active) return;

    // 1x1 remainder over x[16:64]
    const int pxb = (h0 + r) * 128 + w0 + c0;
    const float* xr = xb + 16 * HW + pxb;
    const ull* w1base = s_w + 2688;
#pragma unroll 2
    for (int c = 0; c < 48; c++) {
        ulonglong2 u01 = *(const ulonglong2*)(xr + (size_t)c * HW);
        ulonglong2 u23 = *(const ulonglong2*)(xr + (size_t)c * HW + 4);
        const ull* wp = w1base + (c * 2 + oh) * 10;
        ulonglong2 wA = *(const ulonglong2*)(wp);
        ulonglong2 wB = *(const ulonglong2*)(wp + 2);
        ulonglong2 wC = *(const ulonglong2*)(wp + 4);
        ulonglong2 wD = *(const ulonglong2*)(wp + 6);
        ull w8 = wp[8];
        ull wv[9] = {wA.x, wA.y, wB.x, wB.y, wC.x, wC.y, wD.x, wD.y, w8};
#pragma unroll
        for (int o = 0; o < 9; o++) {
            FMA2(acc2[o][0], wv[o], u01.x, acc2[o][0]);
            FMA2(acc2[o][1], wv[o], u01.y, acc2[o][1]);
            FMA2(acc2[o][2], wv[o], u23.x, acc2[o][2]);
            FMA2(acc2[o][3], wv[o], u23.y, acc2[o][3]);
        }
    }

    if (j == 0) {
        float* mp = g_mask + (size_t)b * 9 * HW + pxb;
#pragma unroll
        for (int o = 0; o < 9; o++) {
            float f[8];
#pragma unroll
            for (int q = 0; q < 4; q++) {
                unsigned lo, hi; UNPACKF(lo, hi, acc2[o][q]);
                f[2 * q]     = 1.f / (1.f + __expf(-__uint_as_float(lo)));
                f[2 * q + 1] = 1.f / (1.f + __expf(-__uint_as_float(hi)));
            }
            float* dst = mp + (size_t)o * HW;
            *reinterpret_cast<float4*>(dst)     = make_float4(f[0], f[1], f[2], f[3]);
            *reinterpret_cast<float4*>(dst + 4) = make_float4(f[4], f[5], f[6], f[7]);
        }
    } else {
        const int slice = b * 4 + (j - 1);
        float* op = g_off + ((size_t)slice * 18 + oh * 9) * HW + pxb;
#pragma unroll
        for (int o = 0; o < 9; o++) {
            float* dst = op + (size_t)o * HW;
            ulonglong2 s0; s0.x = acc2[o][0]; s0.y = acc2[o][1];
            ulonglong2 s1; s1.x = acc2[o][2]; s1.y = acc2[o][3];
            *reinterpret_cast<ulonglong2*>(dst)     = s0;
            *reinterpret_cast<ulonglong2*>(dst + 4) = s1;
        }
    }
}

// ---------------------------------------------------------------------------
// Sampler (known-good R7 config): thread = (b, g, ch-group of 4, h, px-pair).
// 524288 threads.  Corner indices/weights in regs, reused over 4 ch x 2 images.
// ---------------------------------------------------------------------------
__global__ __launch_bounds__(256) void sample_kernel(
    const float* __restrict__ y, float* __restrict__ out)
{
    int idx = blockIdx.x * 256 + threadIdx.x;
    const int w2 = idx & 63;  idx >>= 6;
    const int h  = idx & 127; idx >>= 7;
    const int cg = idx & 3;   idx >>= 2;
    const int g  = idx & 3;
    const int b  = idx >> 2;
    const int w  = w2 * 2;
    const int px = h * 128 + w;

    const float* off = g_off + (size_t)(b * 4 + g) * 18 * HW;
    const float* msk = g_mask + (size_t)b * 9 * HW;
    const float* y1  = y + (size_t)(b * 64 + g * 16 + cg * 4) * HW;
    const float* y2  = y + (size_t)((b + 4) * 64 + g * 16 + cg * 4) * HW;
    float* o1 = out + ((size_t)(b * 64 + g * 16 + cg * 4) * 9) * HW + px;
    float* o2 = out + ((size_t)((b + 4) * 64 + g * 16 + cg * 4) * 9) * HW + px;

    const int dil = 2 * g + 1;

#pragma unroll 1
    for (int k = 0; k < 9; k++) {
        const int ky = k / 3 - 1;
        const int kx = k % 3 - 1;
        const float basey = (float)(h + ky * dil);
        const float basex = (float)(w + kx * dil);

        const float2 dy2 = *reinterpret_cast<const float2*>(off + (size_t)(2 * k) * HW + px);
        const float2 dx2 = *reinterpret_cast<const float2*>(off + (size_t)(2 * k + 1) * HW + px);
        const float2 m2  = *reinterpret_cast<const float2*>(msk + (size_t)k * HW + px);

        int   ci[2][4];
        float cw[2][4];
#pragma unroll
        for (int p = 0; p < 2; p++) {
            float py  = basey + (p ? dy2.y : dy2.x);
            float pxx = basex + (float)p + (p ? dx2.y : dx2.x);
            float m   = p ? m2.y : m2.x;

            float fy0 = floorf(py);
            float fx0 = floorf(pxx);
            float wy = py - fy0;
            float wx = pxx - fx0;

            bool vy0 = (fy0 >= 0.f)  && (fy0 <= 127.f);
            bool vy1 = (fy0 >= -1.f) && (fy0 <= 126.f);
            bool vx0 = (fx0 >= 0.f)  && (fx0 <= 127.f);
            bool vx1 = (fx0 >= -1.f) && (fx0 <= 126.f);

            int y0c = (int)fminf(fmaxf(fy0,       0.f), 127.f);
            int y1c = (int)fminf(fmaxf(fy0 + 1.f, 0.f), 127.f);
            int x0c = (int)fminf(fmaxf(fx0,       0.f), 127.f);
            int x1c = (int)fminf(fmaxf(fx0 + 1.f, 0.f), 127.f);

            float w00 = (1.f - wy) * (1.f - wx) * m; if (!(vy0 && vx0)) w00 = 0.f;
            float w01 = (1.f - wy) * wx        * m; if (!(vy0 && vx1)) w01 = 0.f;
            float w10 = wy        * (1.f - wx) * m; if (!(vy1 && vx0)) w10 = 0.f;
            float w11 = wy        * wx         * m; if (!(vy1 && vx1)) w11 = 0.f;

            ci[p][0] = y0c * 128 + x0c;  cw[p][0] = w00;
            ci[p][1] = y0c * 128 + x1c;  cw[p][1] = w01;
            ci[p][2] = y1c * 128 + x0c;  cw[p][2] = w10;
            ci[p][3] = y1c * 128 + x1c;  cw[p][3] = w11;
        }

#pragma unroll
        for (int c = 0; c < 4; c++) {
            const float* s1 = y1 + (size_t)c * HW;
            const float* s2 = y2 + (size_t)c * HW;

            float r1x = cw[0][0] * s1[ci[0][0]] + cw[0][1] * s1[ci[0][1]]
                      + cw[0][2] * s1[ci[0][2]] + cw[0][3] * s1[ci[0][3]];
            float r1y = cw[1][0] * s1[ci[1][0]] + cw[1][1] * s1[ci[1][1]]
                      + cw[1][2] * s1[ci[1][2]] + cw[1][3] * s1[ci[1][3]];
            float r2x = cw[0][0] * s2[ci[0][0]] + cw[0][1] * s2[ci[0][1]]
                      + cw[0][2] * s2[ci[0][2]] + cw[0][3] * s2[ci[0][3]];
            float r2y = cw[1][0] * s2[ci[1][0]] + cw[1][1] * s2[ci[1][1]]
                      + cw[1][2] * s2[ci[1][2]] + cw[1][3] * s2[ci[1][3]];

            *reinterpret_cast<float2*>(o1 + (size_t)(c * 9 + k) * HW) = make_float2(r1x, r1y);
            *reinterpret_cast<float2*>(o2 + (size_t)(c * 9 + k) * HW) = make_float2(r2x, r2y);
        }
    }
}

// ---------------------------------------------------------------------------
extern "C" void kernel_launch(void* const* d_in, const int* in_sizes, int n_in,
                              void* d_out, int out_size)
{
    const float *x = nullptr, *y = nullptr, *off_pw = nullptr, *off_w = nullptr,
                *off_b = nullptr, *mask_pw = nullptr, *mask_w = nullptr, *mask_b = nullptr;
    for (int i = 0; i < n_in; i++) {
        switch (in_sizes[i]) {
            case 4194304: x       = (const float*)d_in[i]; break;
            case 8388608: y       = (const float*)d_in[i]; break;
            case 9216:    off_pw  = (const float*)d_in[i]; break;
            case 4608:    off_w   = (const float*)d_in[i]; break;
            case 72:      off_b   = (const float*)d_in[i]; break;
            case 2304:    mask_pw = (const float*)d_in[i]; break;
            case 576:     mask_w  = (const float*)d_in[i]; break;
            case 9:       mask_b  = (const float*)d_in[i]; break;
            default: break;
        }
    }
    float* out = (float*)d_out;

    const int head_smem = 4896 * 4 + 3648 * 8;   // 19584 + 29184 = 48768 bytes
    cudaFuncSetAttribute(fused_head_kernel,
                         cudaFuncAttributeMaxDynamicSharedMemorySize, head_smem);

    fold_kernel<<<56, 256>>>(mask_pw, mask_w, off_pw, off_w);
    fused_head_kernel<<<dim3(4, 8, NB * 5), 128, head_smem>>>(x, mask_b, off_b);
    sample_kernel<<<2048, 256>>>(y, out);
}